// round 9
// baseline (speedup 1.0000x reference)
#include <cuda_runtime.h>
#include <math.h>

// ---------------- problem constants ----------------
#define B_SZ   2
#define SEQ    1024
#define DM     1024          // D_MODEL
#define DI     2048          // D_INNER
#define DSTATE 16
#define DCONV  4
#define DTR    64            // DT_RANK
#define XDBLC  96            // DT_RANK + 2*D_STATE
#define MROWS  (B_SZ*SEQ)    // 2048 token rows

// ---------------- scratch (device globals: allocation-free) ----------------
__device__ __align__(128) float g_xz  [(size_t)MROWS * 2 * DI];  // 2048 x 4096
__device__ __align__(128) float g_xc  [(size_t)MROWS * DI];      // 2048 x 2048
__device__ __align__(128) float g_xdbl[(size_t)MROWS * XDBLC];   // 2048 x 96
__device__ __align__(128) float g_dt  [(size_t)MROWS * DI];      // 2048 x 2048
__device__ __align__(128) float g_y   [(size_t)MROWS * DI];      // 2048 x 2048 (gated)
__device__ __align__(128) float g_m   [(size_t)MROWS * DM];      // 2048 x 1024

// ---------------- generic fp32 tiled GEMM ----------------
// C[M,N] = A[M,K] @ B[K,N]   (row-major, arbitrary leading dims)
// EPI: 0 = none, 1 = softplus(v + bias[col])
template<int BM,int BN,int BK,int TM,int TN,int EPI>
__global__ __launch_bounds__((BM/TM)*(BN/TN))
void sgemm(int M, int N, int K,
           const float* __restrict__ A, int lda,
           const float* __restrict__ B, int ldb,
           float*       __restrict__ C, int ldc,
           const float* __restrict__ bias)
{
    constexpr int THREADS = (BM/TM)*(BN/TN);
    __shared__ __align__(16) float As[BK][BM];
    __shared__ __align__(16) float Bs[BK][BN];

    const int tid  = threadIdx.x;
    const int ncol = BN/TN;
    const int tcol = tid % ncol;
    const int trow = tid / ncol;
    const int row0 = blockIdx.y * BM;
    const int col0 = blockIdx.x * BN;

    float acc[TM][TN];
#pragma unroll
    for (int i = 0; i < TM; i++)
#pragma unroll
        for (int j = 0; j < TN; j++) acc[i][j] = 0.f;

    for (int k0 = 0; k0 < K; k0 += BK) {
        // A tile (BM x BK), stored transposed into As[k][m]
        for (int i = 4*tid; i < BM*BK; i += 4*THREADS) {
            int m = i / BK, k = i % BK;            // k % 4 == 0 (BK % 4 == 0)
            float4 v = *reinterpret_cast<const float4*>(
                A + (size_t)(row0 + m) * lda + k0 + k);
            As[k+0][m] = v.x; As[k+1][m] = v.y; As[k+2][m] = v.z; As[k+3][m] = v.w;
        }
        // B tile (BK x BN)
        for (int i = 4*tid; i < BK*BN; i += 4*THREADS) {
            int r = i / BN, c = i % BN;
            *reinterpret_cast<float4*>(&Bs[r][c]) =
                *reinterpret_cast<const float4*>(B + (size_t)(k0 + r) * ldb + col0 + c);
        }
        __syncthreads();

#pragma unroll
        for (int k = 0; k < BK; k++) {
            float rm[TM], rn[TN];
#pragma unroll
            for (int i = 0; i < TM; i++) rm[i] = As[k][trow*TM + i];
#pragma unroll
            for (int j = 0; j < TN; j++) rn[j] = Bs[k][tcol*TN + j];
#pragma unroll
            for (int i = 0; i < TM; i++)
#pragma unroll
                for (int j = 0; j < TN; j++) acc[i][j] += rm[i] * rn[j];
        }
        __syncthreads();
    }

#pragma unroll
    for (int i = 0; i < TM; i++) {
        int r = row0 + trow*TM + i;
#pragma unroll
        for (int j = 0; j < TN; j++) {
            int c = col0 + tcol*TN + j;
            float v = acc[i][j];
            if (EPI == 1) {              // softplus(v + bias)
                v += bias[c];
                v = (v > 20.f) ? v : log1pf(__expf(v));
            }
            C[(size_t)r * ldc + c] = v;
        }
    }
}

// ---------------- causal depthwise conv (width 4) + SiLU ----------------
__global__ void conv_silu(const float* __restrict__ conv_w,
                          const float* __restrict__ conv_b)
{
    int idx = blockIdx.x * blockDim.x + threadIdx.x;
    if (idx >= MROWS * DI) return;
    int d  = idx % DI;
    int bl = idx / DI;
    int l  = bl % SEQ;
    int b  = bl / SEQ;

    float w0 = conv_w[d*DCONV+0], w1 = conv_w[d*DCONV+1];
    float w2 = conv_w[d*DCONV+2], w3 = conv_w[d*DCONV+3];

    float acc = conv_b[d];
    const size_t base = (size_t)(b*SEQ) * (2*DI) + d;
    if (l-3 >= 0) acc += g_xz[base + (size_t)(l-3)*(2*DI)] * w0;
    if (l-2 >= 0) acc += g_xz[base + (size_t)(l-2)*(2*DI)] * w1;
    if (l-1 >= 0) acc += g_xz[base + (size_t)(l-1)*(2*DI)] * w2;
    acc              += g_xz[base + (size_t)(l  )*(2*DI)] * w3;

    // silu
    float s = __fdividef(acc, 1.f + __expf(-acc));
    g_xc[(size_t)bl * DI + d] = s;
}

// ---------------- sequential SSM scan ----------------
// 1 warp per 32 channels of one batch; 16 states per thread in registers.
__global__ void scan_kernel(const float* __restrict__ A_log,
                            const float* __restrict__ D_param)
{
    const int b    = blockIdx.y;
    const int lane = threadIdx.x;
    const int d    = blockIdx.x * 32 + lane;

    float a[DSTATE];
    bool pw = true;
#pragma unroll
    for (int n = 0; n < DSTATE; n++) {
        a[n] = -__expf(A_log[d*DSTATE + n]);
        pw = pw && (fabsf(a[n] + (float)(n+1)) < 1e-4f * (float)(n+1));
    }
    const float Dp = D_param[d];

    float h[DSTATE];
#pragma unroll
    for (int n = 0; n < DSTATE; n++) h[n] = 0.f;

    __shared__ float sBC[32];   // B[0..15], C[0..15] for current (b,l)

    for (int l = 0; l < SEQ; l++) {
        const int row = b*SEQ + l;
        sBC[lane] = g_xdbl[(size_t)row * XDBLC + DTR + lane];
        __syncwarp();

        const float dtv = g_dt[(size_t)row * DI + d];
        const float xv  = g_xc[(size_t)row * DI + d];
        const float zv  = g_xz[(size_t)row * (2*DI) + DI + d];

        float y = 0.f;
        const float dbx = dtv * xv;
        if (pw) {
            // A[d,n] == -(n+1): exp(dt*A_n) = exp(-dt)^(n+1)
            const float p = __expf(-dtv);
            float dA = p;
#pragma unroll
            for (int n = 0; n < DSTATE; n++) {
                h[n] = dA * h[n] + dbx * sBC[n];
                y   += h[n] * sBC[16 + n];
                dA  *= p;
            }
        } else {
#pragma unroll
            for (int n = 0; n < DSTATE; n++) {
                float dA = __expf(dtv * a[n]);
                h[n] = dA * h[n] + dbx * sBC[n];
                y   += h[n] * sBC[16 + n];
            }
        }
        y += xv * Dp;
        const float sg = __fdividef(zv, 1.f + __expf(-zv));  // silu(z)
        g_y[(size_t)row * DI + d] = y * sg;
        __syncwarp();
    }
}

// ---------------- LayerNorm + residual ----------------
__global__ void ln_res(const float* __restrict__ x,
                       const float* __restrict__ gamma,
                       const float* __restrict__ beta,
                       float* __restrict__ out)
{
    const int row = blockIdx.x;          // 0..2047
    const int t   = threadIdx.x;         // 256 threads, 4 elems each
    const float4 v = reinterpret_cast<const float4*>(g_m + (size_t)row*DM)[t];

    float s  = v.x + v.y + v.z + v.w;
    float s2 = v.x*v.x + v.y*v.y + v.z*v.z + v.w*v.w;
#pragma unroll
    for (int o = 16; o > 0; o >>= 1) {
        s  += __shfl_xor_sync(0xffffffffu, s,  o);
        s2 += __shfl_xor_sync(0xffffffffu, s2, o);
    }
    __shared__ float sh[16];
    const int w = t >> 5, ln_ = t & 31;
    if (ln_ == 0) { sh[w] = s; sh[8 + w] = s2; }
    __syncthreads();
    if (t < 8) {
        s = sh[t]; s2 = sh[8 + t];
#pragma unroll
        for (int o = 4; o > 0; o >>= 1) {
            s  += __shfl_xor_sync(0xffu, s,  o);
            s2 += __shfl_xor_sync(0xffu, s2, o);
        }
        if (t == 0) { sh[0] = s; sh[1] = s2; }
    }
    __syncthreads();

    const float mu   = sh[0] * (1.f/DM);
    const float var  = sh[1] * (1.f/DM) - mu*mu;
    const float rstd = rsqrtf(var + 1e-6f);

    const float4 xv = reinterpret_cast<const float4*>(x + (size_t)row*DM)[t];
    const float4 g4 = reinterpret_cast<const float4*>(gamma)[t];
    const float4 b4 = reinterpret_cast<const float4*>(beta)[t];
    float4 o4;
    o4.x = xv.x + (v.x - mu) * rstd * g4.x + b4.x;
    o4.y = xv.y + (v.y - mu) * rstd * g4.y + b4.y;
    o4.z = xv.z + (v.z - mu) * rstd * g4.z + b4.z;
    o4.w = xv.w + (v.w - mu) * rstd * g4.w + b4.w;
    reinterpret_cast<float4*>(out + (size_t)row*DM)[t] = o4;
}

// ---------------- launch ----------------
extern "C" void kernel_launch(void* const* d_in, const int* in_sizes, int n_in,
                              void* d_out, int out_size)
{
    const float* x       = (const float*)d_in[0];   // (2,1024,1024)
    const float* W_in    = (const float*)d_in[1];   // (1024,4096)
    const float* conv_w  = (const float*)d_in[2];   // (2048,4)
    const float* conv_b  = (const float*)d_in[3];   // (2048)
    const float* W_xproj = (const float*)d_in[4];   // (2048,96)
    const float* W_dt    = (const float*)d_in[5];   // (64,2048)
    const float* b_dt    = (const float*)d_in[6];   // (2048)
    const float* A_log   = (const float*)d_in[7];   // (2048,16)
    const float* D_param = (const float*)d_in[8];   // (2048)
    const float* W_out   = (const float*)d_in[9];   // (2048,1024)
    const float* gamma   = (const float*)d_in[10];  // (1024)
    const float* beta    = (const float*)d_in[11];  // (1024)
    float* out = (float*)d_out;

    float *p_xz, *p_xc, *p_xdbl, *p_dt, *p_y, *p_m;
    cudaGetSymbolAddress((void**)&p_xz,   g_xz);
    cudaGetSymbolAddress((void**)&p_xc,   g_xc);
    cudaGetSymbolAddress((void**)&p_xdbl, g_xdbl);
    cudaGetSymbolAddress((void**)&p_dt,   g_dt);
    cudaGetSymbolAddress((void**)&p_y,    g_y);
    cudaGetSymbolAddress((void**)&p_m,    g_m);

    // 1) xz = x @ W_in                     [2048,4096] = [2048,1024]@[1024,4096]
    sgemm<128,128,16,8,8,0><<<dim3(4096/128, 2048/128), 256>>>(
        MROWS, 2*DI, DM, x, DM, W_in, 2*DI, p_xz, 2*DI, nullptr);

    // 2) causal conv + silu -> xc
    conv_silu<<<(MROWS*DI + 255)/256, 256>>>(conv_w, conv_b);

    // 3) x_dbl = xc @ W_xproj              [2048,96]
    sgemm<64,32,8,4,2,0><<<dim3(XDBLC/32, MROWS/64), 256>>>(
        MROWS, XDBLC, DI, p_xc, DI, W_xproj, XDBLC, p_xdbl, XDBLC, nullptr);

    // 4) dt = softplus(dtr @ W_dt + b_dt)  [2048,2048], A = x_dbl[:, :64] (lda=96)
    sgemm<128,128,16,8,8,1><<<dim3(DI/128, MROWS/128), 256>>>(
        MROWS, DI, DTR, p_xdbl, XDBLC, W_dt, DI, p_dt, DI, b_dt);

    // 5) sequential selective scan + D skip + silu(z) gate -> g_y
    scan_kernel<<<dim3(DI/32, B_SZ), 32>>>(A_log, D_param);

    // 6) m = y_gated @ W_out               [2048,1024]
    sgemm<128,128,16,8,8,0><<<dim3(DM/128, MROWS/128), 256>>>(
        MROWS, DM, DI, p_y, DI, W_out, DM, p_m, DM, nullptr);

    // 7) out = x + LayerNorm(m)
    ln_res<<<MROWS, 256>>>(x, gamma, beta, out);
}

// round 10
// speedup vs baseline: 1.2856x; 1.2856x over previous
#include <cuda_runtime.h>
#include <cuda_bf16.h>
#include <math.h>

// ---------------- problem constants ----------------
#define B_SZ   2
#define SEQ    1024
#define DM     1024          // D_MODEL
#define DI     2048          // D_INNER
#define DSTATE 16
#define DCONV  4
#define DTR    64            // DT_RANK
#define XDBLC  96            // DT_RANK + 2*D_STATE
#define MROWS  (B_SZ*SEQ)    // 2048 token rows

// ---------------- scratch (device globals: allocation-free) ----------------
__device__ __align__(128) float g_xz  [(size_t)MROWS * 2 * DI];  // 2048 x 4096
__device__ __align__(128) float g_xc  [(size_t)MROWS * DI];      // 2048 x 2048
__device__ __align__(128) float g_xdbl[(size_t)MROWS * XDBLC];   // 2048 x 96
__device__ __align__(128) float g_dt  [(size_t)MROWS * DI];      // 2048 x 2048
__device__ __align__(128) float g_y   [(size_t)MROWS * DI];      // 2048 x 2048 (gated)
__device__ __align__(128) float g_m   [(size_t)MROWS * DM];      // 2048 x 1024

// =====================================================================
// Tensor-core GEMM: fp32 via bf16 hi/lo split (3 MMA products)
// C[M,N] = A[M,K] @ B[K,N], row-major. EPI: 0=none, 1=softplus(v+bias[n])
// BM=128, BN=128, BK=32, 256 threads (8 warps, 2x4), warp tile 64x32.
// =====================================================================
#define TBM 128
#define TBN 128
#define TBK 32
#define TPAD 2
#define TBKP (TBK + TPAD)   // 34

__device__ __forceinline__ void mma_bf16(float* d, const unsigned* a, const unsigned* b) {
    asm volatile(
        "mma.sync.aligned.m16n8k16.row.col.f32.bf16.bf16.f32 "
        "{%0,%1,%2,%3}, {%4,%5,%6,%7}, {%8,%9}, {%0,%1,%2,%3};\n"
        : "+f"(d[0]), "+f"(d[1]), "+f"(d[2]), "+f"(d[3])
        : "r"(a[0]), "r"(a[1]), "r"(a[2]), "r"(a[3]), "r"(b[0]), "r"(b[1]));
}

__device__ __forceinline__ void split2(float x, __nv_bfloat16& h, __nv_bfloat16& l) {
    h = __float2bfloat16(x);
    l = __float2bfloat16(x - __bfloat162float(h));
}

template<int EPI>
__global__ __launch_bounds__(256)
void hgemm_split(int M, int N, int K,
                 const float* __restrict__ A, int lda,
                 const float* __restrict__ B, int ldb,
                 float*       __restrict__ C, int ldc,
                 const float* __restrict__ bias)
{
    __shared__ __nv_bfloat16 Ah[TBM][TBKP], Al[TBM][TBKP];
    __shared__ __nv_bfloat16 Bh[TBN][TBKP], Bl[TBN][TBKP];

    const int tid  = threadIdx.x;
    const int lane = tid & 31;
    const int wid  = tid >> 5;
    const int wm   = (wid >> 2) * 64;    // warp row offset in block: 0 / 64
    const int wn   = (wid & 3) * 32;     // warp col offset: 0/32/64/96
    const int row0 = blockIdx.y * TBM;
    const int col0 = blockIdx.x * TBN;
    const int ar   = lane >> 2;          // 0..7
    const int ac   = (lane & 3) * 2;     // 0,2,4,6

    float acc[4][4][4];
#pragma unroll
    for (int i = 0; i < 4; i++)
#pragma unroll
        for (int j = 0; j < 4; j++)
#pragma unroll
            for (int q = 0; q < 4; q++) acc[i][j][q] = 0.f;

    for (int k0 = 0; k0 < K; k0 += TBK) {
        // --- A tile: 128x32 floats, 4 float4 per thread, convert to hi/lo ---
#pragma unroll
        for (int it = 0; it < 4; it++) {
            int i = tid * 4 + it * 1024;
            int m = i >> 5;          // / TBK
            int k = i & 31;          // multiple of 4
            float4 v = *reinterpret_cast<const float4*>(
                A + (size_t)(row0 + m) * lda + k0 + k);
            split2(v.x, Ah[m][k+0], Al[m][k+0]);
            split2(v.y, Ah[m][k+1], Al[m][k+1]);
            split2(v.z, Ah[m][k+2], Al[m][k+2]);
            split2(v.w, Ah[m][k+3], Al[m][k+3]);
        }
        // --- B tile: 32x128 floats, store transposed [n][k] ---
#pragma unroll
        for (int it = 0; it < 4; it++) {
            int i = tid * 4 + it * 1024;
            int k = i >> 7;          // / TBN
            int n = i & 127;         // multiple of 4
            float4 v = *reinterpret_cast<const float4*>(
                B + (size_t)(k0 + k) * ldb + col0 + n);
            split2(v.x, Bh[n+0][k], Bl[n+0][k]);
            split2(v.y, Bh[n+1][k], Bl[n+1][k]);
            split2(v.z, Bh[n+2][k], Bl[n+2][k]);
            split2(v.w, Bh[n+3][k], Bl[n+3][k]);
        }
        __syncthreads();

#pragma unroll
        for (int kk = 0; kk < TBK; kk += 16) {
            unsigned ah[4][4], bh[4][2];
#pragma unroll
            for (int mt = 0; mt < 4; mt++) {
                const __nv_bfloat16* p = &Ah[wm + mt*16 + ar][kk + ac];
                ah[mt][0] = *(const unsigned*)p;
                ah[mt][1] = *(const unsigned*)(p + 8*TBKP);
                ah[mt][2] = *(const unsigned*)(p + 8);
                ah[mt][3] = *(const unsigned*)(p + 8*TBKP + 8);
            }
#pragma unroll
            for (int nt = 0; nt < 4; nt++) {
                const __nv_bfloat16* p = &Bh[wn + nt*8 + ar][kk + ac];
                bh[nt][0] = *(const unsigned*)p;
                bh[nt][1] = *(const unsigned*)(p + 8);
            }
            // hi * hi
#pragma unroll
            for (int mt = 0; mt < 4; mt++)
#pragma unroll
                for (int nt = 0; nt < 4; nt++)
                    mma_bf16(acc[mt][nt], ah[mt], bh[nt]);
            // lo * hi
            {
                unsigned al[4][4];
#pragma unroll
                for (int mt = 0; mt < 4; mt++) {
                    const __nv_bfloat16* p = &Al[wm + mt*16 + ar][kk + ac];
                    al[mt][0] = *(const unsigned*)p;
                    al[mt][1] = *(const unsigned*)(p + 8*TBKP);
                    al[mt][2] = *(const unsigned*)(p + 8);
                    al[mt][3] = *(const unsigned*)(p + 8*TBKP + 8);
                }
#pragma unroll
                for (int mt = 0; mt < 4; mt++)
#pragma unroll
                    for (int nt = 0; nt < 4; nt++)
                        mma_bf16(acc[mt][nt], al[mt], bh[nt]);
            }
            // hi * lo
            {
                unsigned bl[4][2];
#pragma unroll
                for (int nt = 0; nt < 4; nt++) {
                    const __nv_bfloat16* p = &Bl[wn + nt*8 + ar][kk + ac];
                    bl[nt][0] = *(const unsigned*)p;
                    bl[nt][1] = *(const unsigned*)(p + 8);
                }
#pragma unroll
                for (int mt = 0; mt < 4; mt++)
#pragma unroll
                    for (int nt = 0; nt < 4; nt++)
                        mma_bf16(acc[mt][nt], ah[mt], bl[nt]);
            }
        }
        __syncthreads();
    }

    // epilogue
#pragma unroll
    for (int mt = 0; mt < 4; mt++) {
#pragma unroll
        for (int nt = 0; nt < 4; nt++) {
            int m = row0 + wm + mt*16 + ar;
            int n = col0 + wn + nt*8 + ac;
            float v0 = acc[mt][nt][0], v1 = acc[mt][nt][1];
            float v2 = acc[mt][nt][2], v3 = acc[mt][nt][3];
            if (EPI == 1) {
                float b0 = bias[n], b1 = bias[n+1];
                v0 += b0; v1 += b1; v2 += b0; v3 += b1;
                v0 = (v0 > 20.f) ? v0 : log1pf(__expf(v0));
                v1 = (v1 > 20.f) ? v1 : log1pf(__expf(v1));
                v2 = (v2 > 20.f) ? v2 : log1pf(__expf(v2));
                v3 = (v3 > 20.f) ? v3 : log1pf(__expf(v3));
            }
            *reinterpret_cast<float2*>(&C[(size_t)m * ldc + n])       = make_float2(v0, v1);
            *reinterpret_cast<float2*>(&C[(size_t)(m + 8) * ldc + n]) = make_float2(v2, v3);
        }
    }
}

// ---------------- generic fp32 tiled GEMM (kept for the small x_dbl GEMM) ----------------
template<int BM,int BN,int BK,int TM,int TN,int EPI>
__global__ __launch_bounds__((BM/TM)*(BN/TN))
void sgemm(int M, int N, int K,
           const float* __restrict__ A, int lda,
           const float* __restrict__ B, int ldb,
           float*       __restrict__ C, int ldc,
           const float* __restrict__ bias)
{
    constexpr int THREADS = (BM/TM)*(BN/TN);
    __shared__ __align__(16) float As[BK][BM];
    __shared__ __align__(16) float Bs[BK][BN];

    const int tid  = threadIdx.x;
    const int ncol = BN/TN;
    const int tcol = tid % ncol;
    const int trow = tid / ncol;
    const int row0 = blockIdx.y * BM;
    const int col0 = blockIdx.x * BN;

    float acc[TM][TN];
#pragma unroll
    for (int i = 0; i < TM; i++)
#pragma unroll
        for (int j = 0; j < TN; j++) acc[i][j] = 0.f;

    for (int k0 = 0; k0 < K; k0 += BK) {
        for (int i = 4*tid; i < BM*BK; i += 4*THREADS) {
            int m = i / BK, k = i % BK;
            float4 v = *reinterpret_cast<const float4*>(
                A + (size_t)(row0 + m) * lda + k0 + k);
            As[k+0][m] = v.x; As[k+1][m] = v.y; As[k+2][m] = v.z; As[k+3][m] = v.w;
        }
        for (int i = 4*tid; i < BK*BN; i += 4*THREADS) {
            int r = i / BN, c = i % BN;
            *reinterpret_cast<float4*>(&Bs[r][c]) =
                *reinterpret_cast<const float4*>(B + (size_t)(k0 + r) * ldb + col0 + c);
        }
        __syncthreads();

#pragma unroll
        for (int k = 0; k < BK; k++) {
            float rm[TM], rn[TN];
#pragma unroll
            for (int i = 0; i < TM; i++) rm[i] = As[k][trow*TM + i];
#pragma unroll
            for (int j = 0; j < TN; j++) rn[j] = Bs[k][tcol*TN + j];
#pragma unroll
            for (int i = 0; i < TM; i++)
#pragma unroll
                for (int j = 0; j < TN; j++) acc[i][j] += rm[i] * rn[j];
        }
        __syncthreads();
    }

#pragma unroll
    for (int i = 0; i < TM; i++) {
        int r = row0 + trow*TM + i;
#pragma unroll
        for (int j = 0; j < TN; j++) {
            int c = col0 + tcol*TN + j;
            float v = acc[i][j];
            if (EPI == 1) {
                v += bias[c];
                v = (v > 20.f) ? v : log1pf(__expf(v));
            }
            C[(size_t)r * ldc + c] = v;
        }
    }
}

// ---------------- causal depthwise conv (width 4) + SiLU ----------------
__global__ void conv_silu(const float* __restrict__ conv_w,
                          const float* __restrict__ conv_b)
{
    int idx = blockIdx.x * blockDim.x + threadIdx.x;
    if (idx >= MROWS * DI) return;
    int d  = idx % DI;
    int bl = idx / DI;
    int l  = bl % SEQ;
    int b  = bl / SEQ;

    float w0 = conv_w[d*DCONV+0], w1 = conv_w[d*DCONV+1];
    float w2 = conv_w[d*DCONV+2], w3 = conv_w[d*DCONV+3];

    float acc = conv_b[d];
    const size_t base = (size_t)(b*SEQ) * (2*DI) + d;
    if (l-3 >= 0) acc += g_xz[base + (size_t)(l-3)*(2*DI)] * w0;
    if (l-2 >= 0) acc += g_xz[base + (size_t)(l-2)*(2*DI)] * w1;
    if (l-1 >= 0) acc += g_xz[base + (size_t)(l-1)*(2*DI)] * w2;
    acc              += g_xz[base + (size_t)(l  )*(2*DI)] * w3;

    float s = __fdividef(acc, 1.f + __expf(-acc));
    g_xc[(size_t)bl * DI + d] = s;
}

// ---------------- sequential SSM scan ----------------
__global__ void scan_kernel(const float* __restrict__ A_log,
                            const float* __restrict__ D_param)
{
    const int b    = blockIdx.y;
    const int lane = threadIdx.x;
    const int d    = blockIdx.x * 32 + lane;

    float a[DSTATE];
    bool pw = true;
#pragma unroll
    for (int n = 0; n < DSTATE; n++) {
        a[n] = -__expf(A_log[d*DSTATE + n]);
        pw = pw && (fabsf(a[n] + (float)(n+1)) < 1e-4f * (float)(n+1));
    }
    const float Dp = D_param[d];

    float h[DSTATE];
#pragma unroll
    for (int n = 0; n < DSTATE; n++) h[n] = 0.f;

    __shared__ float sBC[32];

    for (int l = 0; l < SEQ; l++) {
        const int row = b*SEQ + l;
        sBC[lane] = g_xdbl[(size_t)row * XDBLC + DTR + lane];
        __syncwarp();

        const float dtv = g_dt[(size_t)row * DI + d];
        const float xv  = g_xc[(size_t)row * DI + d];
        const float zv  = g_xz[(size_t)row * (2*DI) + DI + d];

        float y = 0.f;
        const float dbx = dtv * xv;
        if (pw) {
            const float p = __expf(-dtv);
            float dA = p;
#pragma unroll
            for (int n = 0; n < DSTATE; n++) {
                h[n] = dA * h[n] + dbx * sBC[n];
                y   += h[n] * sBC[16 + n];
                dA  *= p;
            }
        } else {
#pragma unroll
            for (int n = 0; n < DSTATE; n++) {
                float dA = __expf(dtv * a[n]);
                h[n] = dA * h[n] + dbx * sBC[n];
                y   += h[n] * sBC[16 + n];
            }
        }
        y += xv * Dp;
        const float sg = __fdividef(zv, 1.f + __expf(-zv));
        g_y[(size_t)row * DI + d] = y * sg;
        __syncwarp();
    }
}

// ---------------- LayerNorm + residual ----------------
__global__ void ln_res(const float* __restrict__ x,
                       const float* __restrict__ gamma,
                       const float* __restrict__ beta,
                       float* __restrict__ out)
{
    const int row = blockIdx.x;
    const int t   = threadIdx.x;
    const float4 v = reinterpret_cast<const float4*>(g_m + (size_t)row*DM)[t];

    float s  = v.x + v.y + v.z + v.w;
    float s2 = v.x*v.x + v.y*v.y + v.z*v.z + v.w*v.w;
#pragma unroll
    for (int o = 16; o > 0; o >>= 1) {
        s  += __shfl_xor_sync(0xffffffffu, s,  o);
        s2 += __shfl_xor_sync(0xffffffffu, s2, o);
    }
    __shared__ float sh[16];
    const int w = t >> 5, ln_ = t & 31;
    if (ln_ == 0) { sh[w] = s; sh[8 + w] = s2; }
    __syncthreads();
    if (t < 8) {
        s = sh[t]; s2 = sh[8 + t];
#pragma unroll
        for (int o = 4; o > 0; o >>= 1) {
            s  += __shfl_xor_sync(0xffu, s,  o);
            s2 += __shfl_xor_sync(0xffu, s2, o);
        }
        if (t == 0) { sh[0] = s; sh[1] = s2; }
    }
    __syncthreads();

    const float mu   = sh[0] * (1.f/DM);
    const float var  = sh[1] * (1.f/DM) - mu*mu;
    const float rstd = rsqrtf(var + 1e-6f);

    const float4 xv = reinterpret_cast<const float4*>(x + (size_t)row*DM)[t];
    const float4 g4 = reinterpret_cast<const float4*>(gamma)[t];
    const float4 b4 = reinterpret_cast<const float4*>(beta)[t];
    float4 o4;
    o4.x = xv.x + (v.x - mu) * rstd * g4.x + b4.x;
    o4.y = xv.y + (v.y - mu) * rstd * g4.y + b4.y;
    o4.z = xv.z + (v.z - mu) * rstd * g4.z + b4.z;
    o4.w = xv.w + (v.w - mu) * rstd * g4.w + b4.w;
    reinterpret_cast<float4*>(out + (size_t)row*DM)[t] = o4;
}

// ---------------- launch ----------------
extern "C" void kernel_launch(void* const* d_in, const int* in_sizes, int n_in,
                              void* d_out, int out_size)
{
    const float* x       = (const float*)d_in[0];
    const float* W_in    = (const float*)d_in[1];
    const float* conv_w  = (const float*)d_in[2];
    const float* conv_b  = (const float*)d_in[3];
    const float* W_xproj = (const float*)d_in[4];
    const float* W_dt    = (const float*)d_in[5];
    const float* b_dt    = (const float*)d_in[6];
    const float* A_log   = (const float*)d_in[7];
    const float* D_param = (const float*)d_in[8];
    const float* W_out   = (const float*)d_in[9];
    const float* gamma   = (const float*)d_in[10];
    const float* beta    = (const float*)d_in[11];
    float* out = (float*)d_out;

    float *p_xz, *p_xc, *p_xdbl, *p_dt, *p_y, *p_m;
    cudaGetSymbolAddress((void**)&p_xz,   g_xz);
    cudaGetSymbolAddress((void**)&p_xc,   g_xc);
    cudaGetSymbolAddress((void**)&p_xdbl, g_xdbl);
    cudaGetSymbolAddress((void**)&p_dt,   g_dt);
    cudaGetSymbolAddress((void**)&p_y,    g_y);
    cudaGetSymbolAddress((void**)&p_m,    g_m);

    // 1) xz = x @ W_in   [2048,4096] -- tensor-core split-bf16
    hgemm_split<0><<<dim3(4096/TBN, 2048/TBM), 256>>>(
        MROWS, 2*DI, DM, x, DM, W_in, 2*DI, p_xz, 2*DI, nullptr);

    // 2) causal conv + silu -> xc
    conv_silu<<<(MROWS*DI + 255)/256, 256>>>(conv_w, conv_b);

    // 3) x_dbl = xc @ W_xproj   [2048,96] -- small, SIMT fp32
    sgemm<64,32,8,4,2,0><<<dim3(XDBLC/32, MROWS/64), 256>>>(
        MROWS, XDBLC, DI, p_xc, DI, W_xproj, XDBLC, p_xdbl, XDBLC, nullptr);

    // 4) dt = softplus(dtr @ W_dt + b_dt)  [2048,2048] -- tensor-core split-bf16
    hgemm_split<1><<<dim3(2048/TBN, 2048/TBM), 256>>>(
        MROWS, DI, DTR, p_xdbl, XDBLC, W_dt, DI, p_dt, DI, b_dt);

    // 5) sequential selective scan + D skip + silu(z) gate -> g_y
    scan_kernel<<<dim3(DI/32, B_SZ), 32>>>(A_log, D_param);

    // 6) m = y_gated @ W_out   [2048,1024] -- tensor-core split-bf16
    hgemm_split<0><<<dim3(1024/TBN, 2048/TBM), 256>>>(
        MROWS, DM, DI, p_y, DI, W_out, DM, p_m, DM, nullptr);

    // 7) out = x + LayerNorm(m)
    ln_res<<<MROWS, 256>>>(x, gamma, beta, out);
}

// round 16
// speedup vs baseline: 2.6025x; 2.0244x over previous
#include <cuda_runtime.h>
#include <cuda_bf16.h>
#include <math.h>

// ---------------- problem constants ----------------
#define B_SZ   2
#define SEQ    1024
#define DM     1024
#define DI     2048
#define DSTATE 16
#define DCONV  4
#define DTR    64
#define XDBLC  96
#define MROWS  (B_SZ*SEQ)
#define NCHUNK 16
#define CLEN   (SEQ/NCHUNK)   // 64

// ---------------- scratch ----------------
__device__ __align__(128) float g_xz  [(size_t)MROWS * 2 * DI];
__device__ __align__(128) float g_xc  [(size_t)MROWS * DI];
__device__ __align__(128) float g_xdbl[(size_t)MROWS * XDBLC];
__device__ __align__(128) float g_dt  [(size_t)MROWS * DI];
__device__ __align__(128) float g_y   [(size_t)MROWS * DI];
__device__ __align__(128) float g_m   [(size_t)MROWS * DM];
// chunk-scan scratch: layout ((b*NCHUNK + c)*DSTATE + n)*DI + d  (coalesced in d)
__device__ __align__(128) float g_hloc[(size_t)B_SZ * NCHUNK * DSTATE * DI];
__device__ __align__(128) float g_hin [(size_t)B_SZ * NCHUNK * DSTATE * DI];
__device__ __align__(128) float g_S   [(size_t)B_SZ * NCHUNK * DI];

// =====================================================================
// Tensor-core GEMM: fp32 via bf16 hi/lo split (3 MMA products)
// =====================================================================
#define TBM 128
#define TBN 128
#define TBK 32
#define TPAD 2
#define TBKP (TBK + TPAD)

__device__ __forceinline__ void mma_bf16(float* d, const unsigned* a, const unsigned* b) {
    asm volatile(
        "mma.sync.aligned.m16n8k16.row.col.f32.bf16.bf16.f32 "
        "{%0,%1,%2,%3}, {%4,%5,%6,%7}, {%8,%9}, {%0,%1,%2,%3};\n"
        : "+f"(d[0]), "+f"(d[1]), "+f"(d[2]), "+f"(d[3])
        : "r"(a[0]), "r"(a[1]), "r"(a[2]), "r"(a[3]), "r"(b[0]), "r"(b[1]));
}

__device__ __forceinline__ void split2(float x, __nv_bfloat16& h, __nv_bfloat16& l) {
    h = __float2bfloat16(x);
    l = __float2bfloat16(x - __bfloat162float(h));
}

template<int EPI>
__global__ __launch_bounds__(256, 2)
void hgemm_split(int M, int N, int K,
                 const float* __restrict__ A, int lda,
                 const float* __restrict__ B, int ldb,
                 float*       __restrict__ C, int ldc,
                 const float* __restrict__ bias)
{
    __shared__ __nv_bfloat16 Ah[TBM][TBKP], Al[TBM][TBKP];
    __shared__ __nv_bfloat16 Bh[TBN][TBKP], Bl[TBN][TBKP];

    const int tid  = threadIdx.x;
    const int lane = tid & 31;
    const int wid  = tid >> 5;
    const int wm   = (wid >> 2) * 64;
    const int wn   = (wid & 3) * 32;
    const int row0 = blockIdx.y * TBM;
    const int col0 = blockIdx.x * TBN;
    const int ar   = lane >> 2;
    const int ac   = (lane & 3) * 2;

    float acc[4][4][4];
#pragma unroll
    for (int i = 0; i < 4; i++)
#pragma unroll
        for (int j = 0; j < 4; j++)
#pragma unroll
            for (int q = 0; q < 4; q++) acc[i][j][q] = 0.f;

    for (int k0 = 0; k0 < K; k0 += TBK) {
#pragma unroll
        for (int it = 0; it < 4; it++) {
            int i = tid * 4 + it * 1024;
            int m = i >> 5;
            int k = i & 31;
            float4 v = *reinterpret_cast<const float4*>(
                A + (size_t)(row0 + m) * lda + k0 + k);
            split2(v.x, Ah[m][k+0], Al[m][k+0]);
            split2(v.y, Ah[m][k+1], Al[m][k+1]);
            split2(v.z, Ah[m][k+2], Al[m][k+2]);
            split2(v.w, Ah[m][k+3], Al[m][k+3]);
        }
#pragma unroll
        for (int it = 0; it < 4; it++) {
            int i = tid * 4 + it * 1024;
            int k = i >> 7;
            int n = i & 127;
            float4 v = *reinterpret_cast<const float4*>(
                B + (size_t)(k0 + k) * ldb + col0 + n);
            split2(v.x, Bh[n+0][k], Bl[n+0][k]);
            split2(v.y, Bh[n+1][k], Bl[n+1][k]);
            split2(v.z, Bh[n+2][k], Bl[n+2][k]);
            split2(v.w, Bh[n+3][k], Bl[n+3][k]);
        }
        __syncthreads();

#pragma unroll
        for (int kk = 0; kk < TBK; kk += 16) {
            unsigned ah[4][4], bh[4][2];
#pragma unroll
            for (int mt = 0; mt < 4; mt++) {
                const __nv_bfloat16* p = &Ah[wm + mt*16 + ar][kk + ac];
                ah[mt][0] = *(const unsigned*)p;
                ah[mt][1] = *(const unsigned*)(p + 8*TBKP);
                ah[mt][2] = *(const unsigned*)(p + 8);
                ah[mt][3] = *(const unsigned*)(p + 8*TBKP + 8);
            }
#pragma unroll
            for (int nt = 0; nt < 4; nt++) {
                const __nv_bfloat16* p = &Bh[wn + nt*8 + ar][kk + ac];
                bh[nt][0] = *(const unsigned*)p;
                bh[nt][1] = *(const unsigned*)(p + 8);
            }
#pragma unroll
            for (int mt = 0; mt < 4; mt++)
#pragma unroll
                for (int nt = 0; nt < 4; nt++)
                    mma_bf16(acc[mt][nt], ah[mt], bh[nt]);
            {
                unsigned al[4][4];
#pragma unroll
                for (int mt = 0; mt < 4; mt++) {
                    const __nv_bfloat16* p = &Al[wm + mt*16 + ar][kk + ac];
                    al[mt][0] = *(const unsigned*)p;
                    al[mt][1] = *(const unsigned*)(p + 8*TBKP);
                    al[mt][2] = *(const unsigned*)(p + 8);
                    al[mt][3] = *(const unsigned*)(p + 8*TBKP + 8);
                }
#pragma unroll
                for (int mt = 0; mt < 4; mt++)
#pragma unroll
                    for (int nt = 0; nt < 4; nt++)
                        mma_bf16(acc[mt][nt], al[mt], bh[nt]);
            }
            {
                unsigned bl[4][2];
#pragma unroll
                for (int nt = 0; nt < 4; nt++) {
                    const __nv_bfloat16* p = &Bl[wn + nt*8 + ar][kk + ac];
                    bl[nt][0] = *(const unsigned*)p;
                    bl[nt][1] = *(const unsigned*)(p + 8);
                }
#pragma unroll
                for (int mt = 0; mt < 4; mt++)
#pragma unroll
                    for (int nt = 0; nt < 4; nt++)
                        mma_bf16(acc[mt][nt], ah[mt], bl[nt]);
            }
        }
        __syncthreads();
    }

#pragma unroll
    for (int mt = 0; mt < 4; mt++) {
#pragma unroll
        for (int nt = 0; nt < 4; nt++) {
            int m = row0 + wm + mt*16 + ar;
            int n = col0 + wn + nt*8 + ac;
            float v0 = acc[mt][nt][0], v1 = acc[mt][nt][1];
            float v2 = acc[mt][nt][2], v3 = acc[mt][nt][3];
            if (EPI == 1) {
                float b0 = bias[n], b1 = bias[n+1];
                v0 += b0; v1 += b1; v2 += b0; v3 += b1;
                v0 = (v0 > 20.f) ? v0 : log1pf(__expf(v0));
                v1 = (v1 > 20.f) ? v1 : log1pf(__expf(v1));
                v2 = (v2 > 20.f) ? v2 : log1pf(__expf(v2));
                v3 = (v3 > 20.f) ? v3 : log1pf(__expf(v3));
            }
            *reinterpret_cast<float2*>(&C[(size_t)m * ldc + n])       = make_float2(v0, v1);
            *reinterpret_cast<float2*>(&C[(size_t)(m + 8) * ldc + n]) = make_float2(v2, v3);
        }
    }
}

// ---------------- small SIMT fp32 GEMM (x_dbl) ----------------
template<int BM,int BN,int BK,int TM,int TN>
__global__ __launch_bounds__((BM/TM)*(BN/TN))
void sgemm(int M, int N, int K,
           const float* __restrict__ A, int lda,
           const float* __restrict__ B, int ldb,
           float*       __restrict__ C, int ldc)
{
    constexpr int THREADS = (BM/TM)*(BN/TN);
    __shared__ __align__(16) float As[BK][BM];
    __shared__ __align__(16) float Bs[BK][BN];

    const int tid  = threadIdx.x;
    const int ncol = BN/TN;
    const int tcol = tid % ncol;
    const int trow = tid / ncol;
    const int row0 = blockIdx.y * BM;
    const int col0 = blockIdx.x * BN;

    float acc[TM][TN];
#pragma unroll
    for (int i = 0; i < TM; i++)
#pragma unroll
        for (int j = 0; j < TN; j++) acc[i][j] = 0.f;

    for (int k0 = 0; k0 < K; k0 += BK) {
        for (int i = 4*tid; i < BM*BK; i += 4*THREADS) {
            int m = i / BK, k = i % BK;
            float4 v = *reinterpret_cast<const float4*>(
                A + (size_t)(row0 + m) * lda + k0 + k);
            As[k+0][m] = v.x; As[k+1][m] = v.y; As[k+2][m] = v.z; As[k+3][m] = v.w;
        }
        for (int i = 4*tid; i < BK*BN; i += 4*THREADS) {
            int r = i / BN, c = i % BN;
            *reinterpret_cast<float4*>(&Bs[r][c]) =
                *reinterpret_cast<const float4*>(B + (size_t)(k0 + r) * ldb + col0 + c);
        }
        __syncthreads();

#pragma unroll
        for (int k = 0; k < BK; k++) {
            float rm[TM], rn[TN];
#pragma unroll
            for (int i = 0; i < TM; i++) rm[i] = As[k][trow*TM + i];
#pragma unroll
            for (int j = 0; j < TN; j++) rn[j] = Bs[k][tcol*TN + j];
#pragma unroll
            for (int i = 0; i < TM; i++)
#pragma unroll
                for (int j = 0; j < TN; j++) acc[i][j] += rm[i] * rn[j];
        }
        __syncthreads();
    }

#pragma unroll
    for (int i = 0; i < TM; i++) {
        int r = row0 + trow*TM + i;
#pragma unroll
        for (int j = 0; j < TN; j++)
            C[(size_t)r * ldc + col0 + tcol*TN + j] = acc[i][j];
    }
}

// ---------------- causal depthwise conv (width 4) + SiLU ----------------
__global__ void conv_silu(const float* __restrict__ conv_w,
                          const float* __restrict__ conv_b)
{
    int idx = blockIdx.x * blockDim.x + threadIdx.x;
    if (idx >= MROWS * DI) return;
    int d  = idx % DI;
    int bl = idx / DI;
    int l  = bl % SEQ;
    int b  = bl / SEQ;

    float w0 = conv_w[d*DCONV+0], w1 = conv_w[d*DCONV+1];
    float w2 = conv_w[d*DCONV+2], w3 = conv_w[d*DCONV+3];

    float acc = conv_b[d];
    const size_t base = (size_t)(b*SEQ) * (2*DI) + d;
    if (l-3 >= 0) acc += g_xz[base + (size_t)(l-3)*(2*DI)] * w0;
    if (l-2 >= 0) acc += g_xz[base + (size_t)(l-2)*(2*DI)] * w1;
    if (l-1 >= 0) acc += g_xz[base + (size_t)(l-1)*(2*DI)] * w2;
    acc              += g_xz[base + (size_t)(l  )*(2*DI)] * w3;

    float s = __fdividef(acc, 1.f + __expf(-acc));
    g_xc[(size_t)bl * DI + d] = s;
}

// =====================================================================
// Chunk-parallel SSM scan: Π exp(dt·a_n) = exp(a_n·Σdt)
// =====================================================================
// Pass A: per-chunk local scan (h_in = 0) -> h_loc, S = Σdt
__global__ void scanA(const float* __restrict__ A_log)
{
    const int b    = blockIdx.y;
    const int c    = blockIdx.z;
    const int lane = threadIdx.x;
    const int d    = blockIdx.x * 32 + lane;

    float a[DSTATE];
    bool pw = true;
#pragma unroll
    for (int n = 0; n < DSTATE; n++) {
        a[n] = -__expf(A_log[d*DSTATE + n]);
        pw = pw && (fabsf(a[n] + (float)(n+1)) < 1e-4f * (float)(n+1));
    }

    float h[DSTATE];
#pragma unroll
    for (int n = 0; n < DSTATE; n++) h[n] = 0.f;
    float S = 0.f;

    __shared__ float sB[16];

    for (int i = 0; i < CLEN; i++) {
        const int row = b*SEQ + c*CLEN + i;
        if (lane < 16) sB[lane] = g_xdbl[(size_t)row * XDBLC + DTR + lane];
        __syncwarp();

        const float dtv = g_dt[(size_t)row * DI + d];
        const float xv  = g_xc[(size_t)row * DI + d];
        const float dbx = dtv * xv;
        S += dtv;

        if (pw) {
            const float p = __expf(-dtv);
            float dA = p;
#pragma unroll
            for (int n = 0; n < DSTATE; n++) {
                h[n] = dA * h[n] + dbx * sB[n];
                dA  *= p;
            }
        } else {
#pragma unroll
            for (int n = 0; n < DSTATE; n++)
                h[n] = __expf(dtv * a[n]) * h[n] + dbx * sB[n];
        }
        __syncwarp();
    }

    const size_t cb = ((size_t)(b*NCHUNK + c));
#pragma unroll
    for (int n = 0; n < DSTATE; n++)
        g_hloc[(cb*DSTATE + n)*DI + d] = h[n];
    g_S[cb*DI + d] = S;
}

// Pass B: sequential over 16 chunks (parallel over d) -> h_in per chunk
__global__ void scanB(const float* __restrict__ A_log)
{
    const int b    = blockIdx.y;
    const int lane = threadIdx.x;
    const int d    = blockIdx.x * 32 + lane;

    float a[DSTATE];
    bool pw = true;
#pragma unroll
    for (int n = 0; n < DSTATE; n++) {
        a[n] = -__expf(A_log[d*DSTATE + n]);
        pw = pw && (fabsf(a[n] + (float)(n+1)) < 1e-4f * (float)(n+1));
    }

    float h[DSTATE];
#pragma unroll
    for (int n = 0; n < DSTATE; n++) h[n] = 0.f;

    for (int c = 0; c < NCHUNK; c++) {
        const size_t cb = (size_t)(b*NCHUNK + c);
#pragma unroll
        for (int n = 0; n < DSTATE; n++)
            g_hin[(cb*DSTATE + n)*DI + d] = h[n];

        const float S = g_S[cb*DI + d];
        if (pw) {
            const float p = __expf(-S);
            float D = p;
#pragma unroll
            for (int n = 0; n < DSTATE; n++) {
                h[n] = D * h[n] + g_hloc[(cb*DSTATE + n)*DI + d];
                D   *= p;
            }
        } else {
#pragma unroll
            for (int n = 0; n < DSTATE; n++)
                h[n] = __expf(a[n] * S) * h[n] + g_hloc[(cb*DSTATE + n)*DI + d];
        }
    }
}

// Pass C: replay each chunk from h_in, emit gated y
__global__ void scanC(const float* __restrict__ A_log,
                      const float* __restrict__ D_param)
{
    const int b    = blockIdx.y;
    const int c    = blockIdx.z;
    const int lane = threadIdx.x;
    const int d    = blockIdx.x * 32 + lane;

    float a[DSTATE];
    bool pw = true;
#pragma unroll
    for (int n = 0; n < DSTATE; n++) {
        a[n] = -__expf(A_log[d*DSTATE + n]);
        pw = pw && (fabsf(a[n] + (float)(n+1)) < 1e-4f * (float)(n+1));
    }
    const float Dp = D_param[d];

    float h[DSTATE];
    const size_t cb = (size_t)(b*NCHUNK + c);
#pragma unroll
    for (int n = 0; n < DSTATE; n++)
        h[n] = g_hin[(cb*DSTATE + n)*DI + d];

    __shared__ float sBC[32];

    for (int i = 0; i < CLEN; i++) {
        const int row = b*SEQ + c*CLEN + i;
        sBC[lane] = g_xdbl[(size_t)row * XDBLC + DTR + lane];
        __syncwarp();

        const float dtv = g_dt[(size_t)row * DI + d];
        const float xv  = g_xc[(size_t)row * DI + d];
        const float zv  = g_xz[(size_t)row * (2*DI) + DI + d];
        const float dbx = dtv * xv;

        float y = 0.f;
        if (pw) {
            const float p = __expf(-dtv);
            float dA = p;
#pragma unroll
            for (int n = 0; n < DSTATE; n++) {
                h[n] = dA * h[n] + dbx * sBC[n];
                y   += h[n] * sBC[16 + n];
                dA  *= p;
            }
        } else {
#pragma unroll
            for (int n = 0; n < DSTATE; n++) {
                h[n] = __expf(dtv * a[n]) * h[n] + dbx * sBC[n];
                y   += h[n] * sBC[16 + n];
            }
        }
        y += xv * Dp;
        const float sg = __fdividef(zv, 1.f + __expf(-zv));
        g_y[(size_t)row * DI + d] = y * sg;
        __syncwarp();
    }
}

// ---------------- LayerNorm + residual ----------------
__global__ void ln_res(const float* __restrict__ x,
                       const float* __restrict__ gamma,
                       const float* __restrict__ beta,
                       float* __restrict__ out)
{
    const int row = blockIdx.x;
    const int t   = threadIdx.x;
    const float4 v = reinterpret_cast<const float4*>(g_m + (size_t)row*DM)[t];

    float s  = v.x + v.y + v.z + v.w;
    float s2 = v.x*v.x + v.y*v.y + v.z*v.z + v.w*v.w;
#pragma unroll
    for (int o = 16; o > 0; o >>= 1) {
        s  += __shfl_xor_sync(0xffffffffu, s,  o);
        s2 += __shfl_xor_sync(0xffffffffu, s2, o);
    }
    __shared__ float sh[16];
    const int w = t >> 5, ln_ = t & 31;
    if (ln_ == 0) { sh[w] = s; sh[8 + w] = s2; }
    __syncthreads();
    if (t < 8) {
        s = sh[t]; s2 = sh[8 + t];
#pragma unroll
        for (int o = 4; o > 0; o >>= 1) {
            s  += __shfl_xor_sync(0xffu, s,  o);
            s2 += __shfl_xor_sync(0xffu, s2, o);
        }
        if (t == 0) { sh[0] = s; sh[1] = s2; }
    }
    __syncthreads();

    const float mu   = sh[0] * (1.f/DM);
    const float var  = sh[1] * (1.f/DM) - mu*mu;
    const float rstd = rsqrtf(var + 1e-6f);

    const float4 xv = reinterpret_cast<const float4*>(x + (size_t)row*DM)[t];
    const float4 g4 = reinterpret_cast<const float4*>(gamma)[t];
    const float4 b4 = reinterpret_cast<const float4*>(beta)[t];
    float4 o4;
    o4.x = xv.x + (v.x - mu) * rstd * g4.x + b4.x;
    o4.y = xv.y + (v.y - mu) * rstd * g4.y + b4.y;
    o4.z = xv.z + (v.z - mu) * rstd * g4.z + b4.z;
    o4.w = xv.w + (v.w - mu) * rstd * g4.w + b4.w;
    reinterpret_cast<float4*>(out + (size_t)row*DM)[t] = o4;
}

// ---------------- launch ----------------
extern "C" void kernel_launch(void* const* d_in, const int* in_sizes, int n_in,
                              void* d_out, int out_size)
{
    const float* x       = (const float*)d_in[0];
    const float* W_in    = (const float*)d_in[1];
    const float* conv_w  = (const float*)d_in[2];
    const float* conv_b  = (const float*)d_in[3];
    const float* W_xproj = (const float*)d_in[4];
    const float* W_dt    = (const float*)d_in[5];
    const float* b_dt    = (const float*)d_in[6];
    const float* A_log   = (const float*)d_in[7];
    const float* D_param = (const float*)d_in[8];
    const float* W_out   = (const float*)d_in[9];
    const float* gamma   = (const float*)d_in[10];
    const float* beta    = (const float*)d_in[11];
    float* out = (float*)d_out;

    float *p_xz, *p_xc, *p_xdbl, *p_dt, *p_y, *p_m;
    cudaGetSymbolAddress((void**)&p_xz,   g_xz);
    cudaGetSymbolAddress((void**)&p_xc,   g_xc);
    cudaGetSymbolAddress((void**)&p_xdbl, g_xdbl);
    cudaGetSymbolAddress((void**)&p_dt,   g_dt);
    cudaGetSymbolAddress((void**)&p_y,    g_y);
    cudaGetSymbolAddress((void**)&p_m,    g_m);

    // 1) xz = x @ W_in   [2048,4096]
    hgemm_split<0><<<dim3(4096/TBN, 2048/TBM), 256>>>(
        MROWS, 2*DI, DM, x, DM, W_in, 2*DI, p_xz, 2*DI, nullptr);

    // 2) conv + silu
    conv_silu<<<(MROWS*DI + 255)/256, 256>>>(conv_w, conv_b);

    // 3) x_dbl = xc @ W_xproj   [2048,96]
    sgemm<64,32,8,4,2><<<dim3(XDBLC/32, MROWS/64), 256>>>(
        MROWS, XDBLC, DI, p_xc, DI, W_xproj, XDBLC, p_xdbl, XDBLC);

    // 4) dt = softplus(dtr @ W_dt + b_dt)  [2048,2048]
    hgemm_split<1><<<dim3(2048/TBN, 2048/TBM), 256>>>(
        MROWS, DI, DTR, p_xdbl, XDBLC, W_dt, DI, p_dt, DI, b_dt);

    // 5) chunk-parallel scan
    scanA<<<dim3(DI/32, B_SZ, NCHUNK), 32>>>(A_log);
    scanB<<<dim3(DI/32, B_SZ), 32>>>(A_log);
    scanC<<<dim3(DI/32, B_SZ, NCHUNK), 32>>>(A_log, D_param);

    // 6) m = y_gated @ W_out   [2048,1024]
    hgemm_split<0><<<dim3(1024/TBN, 2048/TBM), 256>>>(
        MROWS, DM, DI, p_y, DI, W_out, DM, p_m, DM, nullptr);

    // 7) out = x + LayerNorm(m)
    ln_res<<<MROWS, 256>>>(x, gamma, beta, out);
}